// round 5
// baseline (speedup 1.0000x reference)
#include <cuda_runtime.h>
#include <cuda_bf16.h>
#include <math.h>
#include <stdint.h>

// ---------------------------------------------------------------------------
// Problem constants
// ---------------------------------------------------------------------------
constexpr int B  = 8;
constexpr int S  = 1024;
constexpr int D  = 512;
constexpr int H  = 8;
constexpr int DH = 64;
constexpr int BHSD = B * H * S * DH;          // 4,194,304
constexpr int BSD  = B * S * D;               // 4,194,304

// softmax scale folded into Q planes, base-2 domain: 1/sqrt(64) * log2(e)
#define FOLD_F 0.18033688011112042f

// ---------------------------------------------------------------------------
// Device scratch (all bf16 hi/lo plane pairs)
// ---------------------------------------------------------------------------
__device__ __nv_bfloat16 g_Inh[3 * BSD], g_Inl[3 * BSD];   // split Q,K,V inputs
__device__ __nv_bfloat16 g_Qbh[BHSD], g_Qbl[BHSD];         // [bh][s][dh], scaled
__device__ __nv_bfloat16 g_Kbh[BHSD], g_Kbl[BHSD];         // [bh][s][dh]
__device__ __nv_bfloat16 g_Vth[BHSD], g_Vtl[BHSD];         // [bh][dh][s]
__device__ __nv_bfloat16 g_Xh [BHSD], g_Xl [BHSD];         // attn out planes

// weights: [n][k] (k contiguous, ld=512); proj heads stacked n = h*64+e
__device__ __nv_bfloat16 g_Wt_hi [3 * H * DH * D];
__device__ __nv_bfloat16 g_Wt_lo [3 * H * DH * D];
__device__ __nv_bfloat16 g_Wot_hi[D * D];
__device__ __nv_bfloat16 g_Wot_lo[D * D];

// ---------------------------------------------------------------------------
// helpers
// ---------------------------------------------------------------------------
__device__ __forceinline__ void mma_bf16(float* d, const uint32_t* a, const uint32_t* b) {
    asm volatile(
        "mma.sync.aligned.m16n8k16.row.col.f32.bf16.bf16.f32 "
        "{%0,%1,%2,%3}, {%4,%5,%6,%7}, {%8,%9}, {%0,%1,%2,%3};"
        : "+f"(d[0]), "+f"(d[1]), "+f"(d[2]), "+f"(d[3])
        : "r"(a[0]), "r"(a[1]), "r"(a[2]), "r"(a[3]), "r"(b[0]), "r"(b[1]));
}

__device__ __forceinline__ float ex2f(float x) {
    float r;
    asm("ex2.approx.f32 %0, %1;" : "=f"(r) : "f"(x));
    return r;
}

#define CP_ASYNC16(dst_u32, gptr) \
    asm volatile("cp.async.cg.shared.global [%0], [%1], 16;" :: "r"(dst_u32), "l"(gptr))
#define CP_ASYNC_COMMIT() asm volatile("cp.async.commit_group;" ::: "memory")
#define CP_ASYNC_WAIT(n)  asm volatile("cp.async.wait_group %0;" :: "n"(n) : "memory")

__device__ __forceinline__ uint32_t pack_bf16x2(float a, float b, uint32_t& lo) {
    __nv_bfloat162 h = __floats2bfloat162_rn(a, b);
    float2 bk = __bfloat1622float2(h);
    __nv_bfloat162 l = __floats2bfloat162_rn(a - bk.x, b - bk.y);
    lo = *reinterpret_cast<uint32_t*>(&l);
    return *reinterpret_cast<uint32_t*>(&h);
}

// ---------------------------------------------------------------------------
// prep: weight transpose + split, input split
// ---------------------------------------------------------------------------
__global__ void prep_weights(const float* __restrict__ Wq,
                             const float* __restrict__ Wk,
                             const float* __restrict__ Wv,
                             const float* __restrict__ Wo)
{
    int idx = blockIdx.x * blockDim.x + threadIdx.x;   // 0 .. 1048575
    if (idx < 3 * H * DH * D) {
        int k = idx & 511;
        int e = (idx >> 9) & 63;
        int h = (idx >> 15) & 7;
        int p = idx >> 18;
        const float* W = (p == 0) ? Wq : (p == 1) ? Wk : Wv;
        float v = W[h * (D * DH) + k * DH + e];
        __nv_bfloat16 hi = __float2bfloat16(v);
        __nv_bfloat16 lo = __float2bfloat16(v - __bfloat162float(hi));
        g_Wt_hi[idx] = hi;
        g_Wt_lo[idx] = lo;
    } else {
        int j = idx - 3 * H * DH * D;
        int k = j & 511;
        int n = j >> 9;
        float v = Wo[k * 512 + n];
        __nv_bfloat16 hi = __float2bfloat16(v);
        __nv_bfloat16 lo = __float2bfloat16(v - __bfloat162float(hi));
        g_Wot_hi[j] = hi;
        g_Wot_lo[j] = lo;
    }
}

__global__ void split_inputs(const float* __restrict__ Q,
                             const float* __restrict__ K,
                             const float* __restrict__ V)
{
    int i = blockIdx.x * blockDim.x + threadIdx.x;     // 0 .. 3*BSD/4 - 1
    int p = i / (BSD / 4);
    int j = i - p * (BSD / 4);
    const float* src = (p == 0) ? Q : (p == 1) ? K : V;
    float4 v = reinterpret_cast<const float4*>(src)[j];
    uint32_t lo0, lo1;
    uint32_t hi0 = pack_bf16x2(v.x, v.y, lo0);
    uint32_t hi1 = pack_bf16x2(v.z, v.w, lo1);
    *reinterpret_cast<uint2*>(g_Inh + (size_t)p * BSD + (size_t)j * 4) = make_uint2(hi0, hi1);
    *reinterpret_cast<uint2*>(g_Inl + (size_t)p * BSD + (size_t)j * 4) = make_uint2(lo0, lo1);
}

// ---------------------------------------------------------------------------
// GEMM mainloop: acc[2][8][4] += A[128,512] * B[128,512]^T (split bf16, 3 MMA)
// Block 256 (8 warps: mw = w&3 -> 32 rows, nw = w>>2 -> 64 cols).
// K-chunk 32, cp.async double-buffered.
// ---------------------------------------------------------------------------
constexpr int AROW    = 40;                 // padded row (bf16) for 32-k chunk
constexpr int PLANE_E = 128 * AROW;         // elems per plane
constexpr int BUF_E   = 4 * PLANE_E;        // Ah,Al,Bh,Bl
constexpr int GEMM_SMEM = 2 * BUF_E * 2;    // bytes = 81920

__device__ __forceinline__ void gemm_issue_chunk(
    const __nv_bfloat16* Ah_g, const __nv_bfloat16* Al_g,
    const __nv_bfloat16* Bh_g, const __nv_bfloat16* Bl_g,
    uint32_t sbuf, int kk, int tid)
{
    const int r = (tid >> 2);
    const int c = (tid & 3) * 8;
    const size_t go = (size_t)r * 512 + kk + c;
    const size_t go2 = go + (size_t)64 * 512;
    const uint32_t so  = (uint32_t)(r * AROW + c) * 2;
    const uint32_t so2 = so + 64 * AROW * 2;
    CP_ASYNC16(sbuf + so,                   Ah_g + go);
    CP_ASYNC16(sbuf + so2,                  Ah_g + go2);
    CP_ASYNC16(sbuf + PLANE_E * 2 + so,     Al_g + go);
    CP_ASYNC16(sbuf + PLANE_E * 2 + so2,    Al_g + go2);
    CP_ASYNC16(sbuf + PLANE_E * 4 + so,     Bh_g + go);
    CP_ASYNC16(sbuf + PLANE_E * 4 + so2,    Bh_g + go2);
    CP_ASYNC16(sbuf + PLANE_E * 6 + so,     Bl_g + go);
    CP_ASYNC16(sbuf + PLANE_E * 6 + so2,    Bl_g + go2);
    CP_ASYNC_COMMIT();
}

__device__ __forceinline__ void gemm_mainloop_128x128(
    const __nv_bfloat16* Ah_g, const __nv_bfloat16* Al_g,
    const __nv_bfloat16* Bh_g, const __nv_bfloat16* Bl_g,
    float acc[2][8][4], __nv_bfloat16* smem)
{
    const int tid  = threadIdx.x;
    const int wid  = tid >> 5;
    const int lane = tid & 31;
    const int g    = lane >> 2;
    const int t    = lane & 3;
    const int m0   = (wid & 3) * 32;
    const int n0w  = (wid >> 2) * 64;
    const uint32_t sbase = (uint32_t)__cvta_generic_to_shared(smem);

    gemm_issue_chunk(Ah_g, Al_g, Bh_g, Bl_g, sbase, 0, tid);

    for (int ch = 0; ch < 16; ch++) {
        const int bb = ch & 1;
        if (ch + 1 < 16) {
            gemm_issue_chunk(Ah_g, Al_g, Bh_g, Bl_g,
                             sbase + (1 - bb) * BUF_E * 2, (ch + 1) * 32, tid);
            CP_ASYNC_WAIT(1);
        } else {
            CP_ASYNC_WAIT(0);
        }
        __syncthreads();

        const __nv_bfloat16* sb = smem + bb * BUF_E;
        const __nv_bfloat16* sAh = sb;
        const __nv_bfloat16* sAl = sb + PLANE_E;
        const __nv_bfloat16* sBh = sb + 2 * PLANE_E;
        const __nv_bfloat16* sBl = sb + 3 * PLANE_E;

        #pragma unroll
        for (int ks = 0; ks < 2; ks++) {
            uint32_t ah[2][4], al[2][4];
            #pragma unroll
            for (int mf = 0; mf < 2; mf++) {
                int base = (m0 + mf * 16 + g) * AROW + ks * 16 + 2 * t;
                ah[mf][0] = *reinterpret_cast<const uint32_t*>(sAh + base);
                ah[mf][1] = *reinterpret_cast<const uint32_t*>(sAh + base + 8 * AROW);
                ah[mf][2] = *reinterpret_cast<const uint32_t*>(sAh + base + 8);
                ah[mf][3] = *reinterpret_cast<const uint32_t*>(sAh + base + 8 * AROW + 8);
                al[mf][0] = *reinterpret_cast<const uint32_t*>(sAl + base);
                al[mf][1] = *reinterpret_cast<const uint32_t*>(sAl + base + 8 * AROW);
                al[mf][2] = *reinterpret_cast<const uint32_t*>(sAl + base + 8);
                al[mf][3] = *reinterpret_cast<const uint32_t*>(sAl + base + 8 * AROW + 8);
            }
            #pragma unroll
            for (int nf = 0; nf < 8; nf++) {
                int base = (n0w + nf * 8 + g) * AROW + ks * 16 + 2 * t;
                uint32_t bh[2], bl[2];
                bh[0] = *reinterpret_cast<const uint32_t*>(sBh + base);
                bh[1] = *reinterpret_cast<const uint32_t*>(sBh + base + 8);
                bl[0] = *reinterpret_cast<const uint32_t*>(sBl + base);
                bl[1] = *reinterpret_cast<const uint32_t*>(sBl + base + 8);
                #pragma unroll
                for (int mf = 0; mf < 2; mf++) {
                    mma_bf16(acc[mf][nf], ah[mf], bh);
                    mma_bf16(acc[mf][nf], ah[mf], bl);
                    mma_bf16(acc[mf][nf], al[mf], bh);
                }
            }
        }
        __syncthreads();
    }
}

// ---------------------------------------------------------------------------
// QKV projection: grid (B*S/128 = 64, 512/128 = 4, 3), block 256
// ---------------------------------------------------------------------------
__global__ void __launch_bounds__(256)
proj_gemm(const float* __restrict__ bq, const float* __restrict__ bk,
          const float* __restrict__ bv)
{
    extern __shared__ __nv_bfloat16 smem[];
    const int p    = blockIdx.z;
    const int slab = blockIdx.x;
    const int b    = slab >> 3;
    const int s0   = (slab & 7) * 128;
    const int n0   = blockIdx.y * 128;

    const __nv_bfloat16* Ah_g = g_Inh + (size_t)p * BSD + ((size_t)b * S + s0) * D;
    const __nv_bfloat16* Al_g = g_Inl + (size_t)p * BSD + ((size_t)b * S + s0) * D;
    const __nv_bfloat16* Bh_g = g_Wt_hi + (size_t)p * 512 * 512 + (size_t)n0 * 512;
    const __nv_bfloat16* Bl_g = g_Wt_lo + (size_t)p * 512 * 512 + (size_t)n0 * 512;
    const float* bias = ((p == 0) ? bq : (p == 1) ? bk : bv);

    float acc[2][8][4];
    #pragma unroll
    for (int mf = 0; mf < 2; mf++)
        #pragma unroll
        for (int nf = 0; nf < 8; nf++)
            #pragma unroll
            for (int r = 0; r < 4; r++) acc[mf][nf][r] = 0.f;

    gemm_mainloop_128x128(Ah_g, Al_g, Bh_g, Bl_g, acc, smem);

    const int tid  = threadIdx.x;
    const int wid  = tid >> 5;
    const int lane = tid & 31;
    const int g    = lane >> 2;
    const int t    = lane & 3;
    const int m0   = (wid & 3) * 32;
    const int n0w  = (wid >> 2) * 64;
    const float fold = (p == 0) ? FOLD_F : 1.0f;

    __nv_bfloat16* Ph = (p == 0) ? g_Qbh : (p == 1) ? g_Kbh : g_Vth;
    __nv_bfloat16* Pl = (p == 0) ? g_Qbl : (p == 1) ? g_Kbl : g_Vtl;

    #pragma unroll
    for (int mf = 0; mf < 2; mf++) {
        #pragma unroll
        for (int nf = 0; nf < 8; nf++) {
            const int n  = n0 + n0w + nf * 8 + 2 * t;
            const int h  = n >> 6;
            const int e  = n & 63;
            const int s  = s0 + m0 + mf * 16 + g;
            const float b0 = bias[n], b1 = bias[n + 1];
            float v00 = (acc[mf][nf][0] + b0) * fold;
            float v01 = (acc[mf][nf][1] + b1) * fold;
            float v10 = (acc[mf][nf][2] + b0) * fold;
            float v11 = (acc[mf][nf][3] + b1) * fold;
            if (p < 2) {
                const size_t base = ((size_t)(b * 8 + h) * S + s) * 64 + e;
                uint32_t lo0, lo1;
                uint32_t hi0 = pack_bf16x2(v00, v01, lo0);
                uint32_t hi1 = pack_bf16x2(v10, v11, lo1);
                *reinterpret_cast<uint32_t*>(Ph + base) = hi0;
                *reinterpret_cast<uint32_t*>(Pl + base) = lo0;
                *reinterpret_cast<uint32_t*>(Ph + base + 8 * 64) = hi1;
                *reinterpret_cast<uint32_t*>(Pl + base + 8 * 64) = lo1;
            } else {
                // transposed planes [bh][dh][S]
                const size_t hbv = (size_t)(b * 8 + h) * DH * S;
                float vv[4] = {v00, v01, v10, v11};
                int ee[4] = {e, e + 1, e, e + 1};
                int ss[4] = {s, s, s + 8, s + 8};
                #pragma unroll
                for (int q = 0; q < 4; q++) {
                    __nv_bfloat16 hi = __float2bfloat16(vv[q]);
                    __nv_bfloat16 lo = __float2bfloat16(vv[q] - __bfloat162float(hi));
                    size_t a = hbv + (size_t)ee[q] * S + ss[q];
                    Ph[a] = hi;
                    Pl[a] = lo;
                }
            }
        }
    }
}

// ---------------------------------------------------------------------------
// Output projection: grid (B*1024/128 = 64, 4), block 256
// ---------------------------------------------------------------------------
__global__ void __launch_bounds__(256)
oproj_gemm(const float* __restrict__ bo, float* __restrict__ out)
{
    extern __shared__ __nv_bfloat16 smem[];
    const int slab = blockIdx.x;
    const int n0   = blockIdx.y * 128;

    const __nv_bfloat16* Ah_g = g_Xh + (size_t)slab * 128 * 512;
    const __nv_bfloat16* Al_g = g_Xl + (size_t)slab * 128 * 512;
    const __nv_bfloat16* Bh_g = g_Wot_hi + (size_t)n0 * 512;
    const __nv_bfloat16* Bl_g = g_Wot_lo + (size_t)n0 * 512;

    float acc[2][8][4];
    #pragma unroll
    for (int mf = 0; mf < 2; mf++)
        #pragma unroll
        for (int nf = 0; nf < 8; nf++)
            #pragma unroll
            for (int r = 0; r < 4; r++) acc[mf][nf][r] = 0.f;

    gemm_mainloop_128x128(Ah_g, Al_g, Bh_g, Bl_g, acc, smem);

    const int tid  = threadIdx.x;
    const int wid  = tid >> 5;
    const int lane = tid & 31;
    const int g    = lane >> 2;
    const int t    = lane & 3;
    const int m0   = (wid & 3) * 32;
    const int n0w  = (wid >> 2) * 64;

    float* obase = out + (size_t)slab * 128 * 512 + n0;
    #pragma unroll
    for (int mf = 0; mf < 2; mf++) {
        #pragma unroll
        for (int nf = 0; nf < 8; nf++) {
            const int row = m0 + mf * 16 + g;
            const int col = n0w + nf * 8 + 2 * t;
            const float b0 = bo[n0 + col], b1 = bo[n0 + col + 1];
            *reinterpret_cast<float2*>(obase + (size_t)row * 512 + col) =
                make_float2(acc[mf][nf][0] + b0, acc[mf][nf][1] + b1);
            *reinterpret_cast<float2*>(obase + (size_t)(row + 8) * 512 + col) =
                make_float2(acc[mf][nf][2] + b0, acc[mf][nf][3] + b1);
        }
    }
}

// ---------------------------------------------------------------------------
// Flash attention on HMMA bf16 split (R4 body, plane epilogue).
// grid (16, 64), block 128.
// ---------------------------------------------------------------------------
constexpr int SPAD  = 72;
constexpr int PLANE = 64 * SPAD;
constexpr int ABUF  = 4 * PLANE;
constexpr int ATTN_SMEM = 2 * ABUF * 2;    // 73728 B

__device__ __forceinline__ void attn_issue_tile(
    const __nv_bfloat16* Khp, const __nv_bfloat16* Klp,
    const __nv_bfloat16* Vhp, const __nv_bfloat16* Vlp,
    __nv_bfloat16* sbuf, int kv0, int tid)
{
    #pragma unroll
    for (int i = 0; i < 4; i++) {
        int idx = tid + i * 128;
        int row = idx >> 3, c = (idx & 7) * 8;
        uint32_t d0 = (uint32_t)__cvta_generic_to_shared(sbuf + row * SPAD + c);
        CP_ASYNC16(d0, Khp + (size_t)(kv0 + row) * 64 + c);
        uint32_t d1 = (uint32_t)__cvta_generic_to_shared(sbuf + PLANE + row * SPAD + c);
        CP_ASYNC16(d1, Klp + (size_t)(kv0 + row) * 64 + c);
        uint32_t d2 = (uint32_t)__cvta_generic_to_shared(sbuf + 2 * PLANE + row * SPAD + c);
        CP_ASYNC16(d2, Vhp + (size_t)row * S + kv0 + c);
        uint32_t d3 = (uint32_t)__cvta_generic_to_shared(sbuf + 3 * PLANE + row * SPAD + c);
        CP_ASYNC16(d3, Vlp + (size_t)row * S + kv0 + c);
    }
    CP_ASYNC_COMMIT();
}

__global__ void __launch_bounds__(128, 3) attn_mma()
{
    extern __shared__ __nv_bfloat16 smatt[];
    const int tid  = threadIdx.x;
    const int w    = tid >> 5;
    const int lane = tid & 31;
    const int g    = lane >> 2;
    const int t    = lane & 3;
    const int bh   = blockIdx.y;
    const int q0   = blockIdx.x * 64;
    const size_t hb = (size_t)bh * S * DH;

    const __nv_bfloat16* Qhp = g_Qbh + hb;
    const __nv_bfloat16* Qlp = g_Qbl + hb;
    const __nv_bfloat16* Khp = g_Kbh + hb;
    const __nv_bfloat16* Klp = g_Kbl + hb;
    const __nv_bfloat16* Vhp = g_Vth + hb;
    const __nv_bfloat16* Vlp = g_Vtl + hb;

    uint32_t qh[4][4], ql[4][4];
    const int r0 = q0 + w * 16 + g;
    #pragma unroll
    for (int ks = 0; ks < 4; ks++) {
        int c0 = ks * 16 + 2 * t;
        qh[ks][0] = *reinterpret_cast<const uint32_t*>(Qhp + (size_t)r0 * 64 + c0);
        qh[ks][1] = *reinterpret_cast<const uint32_t*>(Qhp + (size_t)(r0 + 8) * 64 + c0);
        qh[ks][2] = *reinterpret_cast<const uint32_t*>(Qhp + (size_t)r0 * 64 + c0 + 8);
        qh[ks][3] = *reinterpret_cast<const uint32_t*>(Qhp + (size_t)(r0 + 8) * 64 + c0 + 8);
        ql[ks][0] = *reinterpret_cast<const uint32_t*>(Qlp + (size_t)r0 * 64 + c0);
        ql[ks][1] = *reinterpret_cast<const uint32_t*>(Qlp + (size_t)(r0 + 8) * 64 + c0);
        ql[ks][2] = *reinterpret_cast<const uint32_t*>(Qlp + (size_t)r0 * 64 + c0 + 8);
        ql[ks][3] = *reinterpret_cast<const uint32_t*>(Qlp + (size_t)(r0 + 8) * 64 + c0 + 8);
    }

    float O[8][4];
    #pragma unroll
    for (int nf = 0; nf < 8; nf++)
        #pragma unroll
        for (int r = 0; r < 4; r++) O[nf][r] = 0.f;
    float ma = -INFINITY, mb = -INFINITY, la = 0.f, lb = 0.f;

    attn_issue_tile(Khp, Klp, Vhp, Vlp, smatt, 0, tid);

    for (int kt = 0; kt < 16; kt++) {
        const int bb = kt & 1;
        if (kt + 1 < 16) {
            attn_issue_tile(Khp, Klp, Vhp, Vlp, smatt + (1 - bb) * ABUF,
                            (kt + 1) * 64, tid);
            CP_ASYNC_WAIT(1);
        } else {
            CP_ASYNC_WAIT(0);
        }
        __syncthreads();

        const __nv_bfloat16* sb = smatt + bb * ABUF;

        float sc[8][4];
        #pragma unroll
        for (int nf = 0; nf < 8; nf++)
            #pragma unroll
            for (int r = 0; r < 4; r++) sc[nf][r] = 0.f;

        #pragma unroll
        for (int ks = 0; ks < 4; ks++) {
            #pragma unroll
            for (int nf = 0; nf < 8; nf++) {
                int base = (nf * 8 + g) * SPAD + ks * 16 + 2 * t;
                uint32_t kh[2], kl[2];
                kh[0] = *reinterpret_cast<const uint32_t*>(sb + base);
                kh[1] = *reinterpret_cast<const uint32_t*>(sb + base + 8);
                kl[0] = *reinterpret_cast<const uint32_t*>(sb + PLANE + base);
                kl[1] = *reinterpret_cast<const uint32_t*>(sb + PLANE + base + 8);
                mma_bf16(sc[nf], qh[ks], kh);
                mma_bf16(sc[nf], qh[ks], kl);
                mma_bf16(sc[nf], ql[ks], kh);
            }
        }

        float mxa = sc[0][0], mxb = sc[0][2];
        #pragma unroll
        for (int nf = 0; nf < 8; nf++) {
            mxa = fmaxf(mxa, fmaxf(sc[nf][0], sc[nf][1]));
            mxb = fmaxf(mxb, fmaxf(sc[nf][2], sc[nf][3]));
        }
        mxa = fmaxf(mxa, __shfl_xor_sync(0xffffffffu, mxa, 1));
        mxa = fmaxf(mxa, __shfl_xor_sync(0xffffffffu, mxa, 2));
        mxb = fmaxf(mxb, __shfl_xor_sync(0xffffffffu, mxb, 1));
        mxb = fmaxf(mxb, __shfl_xor_sync(0xffffffffu, mxb, 2));
        float mna = fmaxf(ma, mxa), mnb = fmaxf(mb, mxb);
        float aa = ex2f(ma - mna), ab = ex2f(mb - mnb);
        ma = mna; mb = mnb;
        float rsa = 0.f, rsb = 0.f;
        #pragma unroll
        for (int nf = 0; nf < 8; nf++) {
            sc[nf][0] = ex2f(sc[nf][0] - mna);
            sc[nf][1] = ex2f(sc[nf][1] - mna);
            sc[nf][2] = ex2f(sc[nf][2] - mnb);
            sc[nf][3] = ex2f(sc[nf][3] - mnb);
            rsa += sc[nf][0] + sc[nf][1];
            rsb += sc[nf][2] + sc[nf][3];
        }
        rsa += __shfl_xor_sync(0xffffffffu, rsa, 1);
        rsa += __shfl_xor_sync(0xffffffffu, rsa, 2);
        rsb += __shfl_xor_sync(0xffffffffu, rsb, 1);
        rsb += __shfl_xor_sync(0xffffffffu, rsb, 2);
        la = la * aa + rsa;
        lb = lb * ab + rsb;
        #pragma unroll
        for (int nf = 0; nf < 8; nf++) {
            O[nf][0] *= aa; O[nf][1] *= aa;
            O[nf][2] *= ab; O[nf][3] *= ab;
        }

        #pragma unroll
        for (int ks = 0; ks < 4; ks++) {
            uint32_t ph[4], pl[4];
            ph[0] = pack_bf16x2(sc[2 * ks][0],     sc[2 * ks][1],     pl[0]);
            ph[1] = pack_bf16x2(sc[2 * ks][2],     sc[2 * ks][3],     pl[1]);
            ph[2] = pack_bf16x2(sc[2 * ks + 1][0], sc[2 * ks + 1][1], pl[2]);
            ph[3] = pack_bf16x2(sc[2 * ks + 1][2], sc[2 * ks + 1][3], pl[3]);

            #pragma unroll
            for (int nf = 0; nf < 8; nf++) {
                int base = (nf * 8 + g) * SPAD + ks * 16 + 2 * t;
                uint32_t vh[2], vl[2];
                vh[0] = *reinterpret_cast<const uint32_t*>(sb + 2 * PLANE + base);
                vh[1] = *reinterpret_cast<const uint32_t*>(sb + 2 * PLANE + base + 8);
                vl[0] = *reinterpret_cast<const uint32_t*>(sb + 3 * PLANE + base);
                vl[1] = *reinterpret_cast<const uint32_t*>(sb + 3 * PLANE + base + 8);
                mma_bf16(O[nf], ph, vh);
                mma_bf16(O[nf], ph, vl);
                mma_bf16(O[nf], pl, vh);
            }
        }
        __syncthreads();
    }

    // ---- epilogue: write X bf16 hi/lo planes ----
    float ia = 1.0f / la, ib = 1.0f / lb;
    #pragma unroll
    for (int nf = 0; nf < 8; nf++) {
        int c = nf * 8 + 2 * t;
        size_t a0 = hb + (size_t)r0 * 64 + c;
        size_t a1 = hb + (size_t)(r0 + 8) * 64 + c;
        uint32_t lo0, lo1;
        uint32_t hi0 = pack_bf16x2(O[nf][0] * ia, O[nf][1] * ia, lo0);
        uint32_t hi1 = pack_bf16x2(O[nf][2] * ib, O[nf][3] * ib, lo1);
        *reinterpret_cast<uint32_t*>(g_Xh + a0) = hi0;
        *reinterpret_cast<uint32_t*>(g_Xl + a0) = lo0;
        *reinterpret_cast<uint32_t*>(g_Xh + a1) = hi1;
        *reinterpret_cast<uint32_t*>(g_Xl + a1) = lo1;
    }
}

// ---------------------------------------------------------------------------
extern "C" void kernel_launch(void* const* d_in, const int* in_sizes, int n_in,
                              void* d_out, int out_size)
{
    const float* Q  = (const float*)d_in[0];
    const float* K  = (const float*)d_in[1];
    const float* V  = (const float*)d_in[2];
    const float* Wq = (const float*)d_in[3];
    const float* bq = (const float*)d_in[4];
    const float* Wk = (const float*)d_in[5];
    const float* bk = (const float*)d_in[6];
    const float* Wv = (const float*)d_in[7];
    const float* bv = (const float*)d_in[8];
    const float* Wo = (const float*)d_in[9];
    const float* bo = (const float*)d_in[10];
    float* out = (float*)d_out;

    // 0) weight + input splits
    prep_weights<<<4096, 256>>>(Wq, Wk, Wv, Wo);
    split_inputs<<<3 * BSD / 4 / 256, 256>>>(Q, K, V);

    // 1) QKV projections
    cudaFuncSetAttribute(proj_gemm, cudaFuncAttributeMaxDynamicSharedMemorySize, GEMM_SMEM);
    proj_gemm<<<dim3(B * S / 128, 4, 3), 256, GEMM_SMEM>>>(bq, bk, bv);

    // 2) attention
    cudaFuncSetAttribute(attn_mma, cudaFuncAttributeMaxDynamicSharedMemorySize, ATTN_SMEM);
    attn_mma<<<dim3(S / 64, B * H), 128, ATTN_SMEM>>>();

    // 3) output projection
    cudaFuncSetAttribute(oproj_gemm, cudaFuncAttributeMaxDynamicSharedMemorySize, GEMM_SMEM);
    oproj_gemm<<<dim3(B * 1024 / 128, 4), 256, GEMM_SMEM>>>(bo, out);
}

// round 6
// speedup vs baseline: 1.0293x; 1.0293x over previous
#include <cuda_runtime.h>
#include <cuda_bf16.h>
#include <math.h>
#include <stdint.h>

// ---------------------------------------------------------------------------
// Problem constants
// ---------------------------------------------------------------------------
constexpr int B  = 8;
constexpr int S  = 1024;
constexpr int D  = 512;
constexpr int H  = 8;
constexpr int DH = 64;
constexpr int BHSD = B * H * S * DH;

// softmax scale folded into Q planes, base-2 domain: 1/sqrt(64) * log2(e)
#define FOLD_F 0.18033688011112042f

// ---------------------------------------------------------------------------
// Device scratch
// ---------------------------------------------------------------------------
__device__ __nv_bfloat16 g_Qbh[BHSD], g_Qbl[BHSD];   // [bh][s][dh], scale folded
__device__ __nv_bfloat16 g_Kbh[BHSD], g_Kbl[BHSD];   // [bh][s][dh]
__device__ __nv_bfloat16 g_Vth[BHSD], g_Vtl[BHSD];   // [bh][dh][s]  (transposed)
__device__ __nv_bfloat16 g_Xh [BHSD], g_Xl [BHSD];   // attn out planes [bh][s][dh]

// Pre-transposed, bf16-split weight planes: [n][k] layout (k contiguous, ld=512)
__device__ __nv_bfloat16 g_Wt_hi [3 * H * DH * D];
__device__ __nv_bfloat16 g_Wt_lo [3 * H * DH * D];
__device__ __nv_bfloat16 g_Wot_hi[D * D];
__device__ __nv_bfloat16 g_Wot_lo[D * D];

// ---------------------------------------------------------------------------
// helpers
// ---------------------------------------------------------------------------
__device__ __forceinline__ void mma_bf16(float* d, const uint32_t* a, const uint32_t* b) {
    asm volatile(
        "mma.sync.aligned.m16n8k16.row.col.f32.bf16.bf16.f32 "
        "{%0,%1,%2,%3}, {%4,%5,%6,%7}, {%8,%9}, {%0,%1,%2,%3};"
        : "+f"(d[0]), "+f"(d[1]), "+f"(d[2]), "+f"(d[3])
        : "r"(a[0]), "r"(a[1]), "r"(a[2]), "r"(a[3]), "r"(b[0]), "r"(b[1]));
}

__device__ __forceinline__ float ex2f(float x) {
    float r;
    asm("ex2.approx.f32 %0, %1;" : "=f"(r) : "f"(x));
    return r;
}

#define CP_ASYNC16(dst_u32, gptr) \
    asm volatile("cp.async.cg.shared.global [%0], [%1], 16;" :: "r"(dst_u32), "l"(gptr))
#define CP_ASYNC_COMMIT() asm volatile("cp.async.commit_group;" ::: "memory")
#define CP_ASYNC_WAIT(n)  asm volatile("cp.async.wait_group %0;" :: "n"(n) : "memory")

__device__ __forceinline__ uint32_t pack_bf16x2(float a, float b, uint32_t& lo) {
    __nv_bfloat162 h = __floats2bfloat162_rn(a, b);
    float2 bk = __bfloat1622float2(h);
    __nv_bfloat162 l = __floats2bfloat162_rn(a - bk.x, b - bk.y);
    lo = *reinterpret_cast<uint32_t*>(&l);
    return *reinterpret_cast<uint32_t*>(&h);
}

// ---------------------------------------------------------------------------
// Weight prep: transpose + bf16 split
// ---------------------------------------------------------------------------
__global__ void prep_weights(const float* __restrict__ Wq,
                             const float* __restrict__ Wk,
                             const float* __restrict__ Wv,
                             const float* __restrict__ Wo)
{
    int idx = blockIdx.x * blockDim.x + threadIdx.x;   // 0 .. 1048575
    if (idx < 3 * H * DH * D) {
        int k = idx & 511;
        int e = (idx >> 9) & 63;
        int h = (idx >> 15) & 7;
        int p = idx >> 18;
        const float* W = (p == 0) ? Wq : (p == 1) ? Wk : Wv;
        float v = W[h * (D * DH) + k * DH + e];
        __nv_bfloat16 hi = __float2bfloat16(v);
        __nv_bfloat16 lo = __float2bfloat16(v - __bfloat162float(hi));
        g_Wt_hi[idx] = hi;
        g_Wt_lo[idx] = lo;
    } else {
        int j = idx - 3 * H * DH * D;
        int k = j & 511;
        int n = j >> 9;
        float v = Wo[k * 512 + n];
        __nv_bfloat16 hi = __float2bfloat16(v);
        __nv_bfloat16 lo = __float2bfloat16(v - __bfloat162float(hi));
        g_Wot_hi[j] = hi;
        g_Wot_lo[j] = lo;
    }
}

// ---------------------------------------------------------------------------
// GEMM body (R4-proven): Out[128,64] = A[128,512] * B[64,512]^T + bias
// A_PLANES=false: A fp32, converted+split in-kernel.
// A_PLANES=true : A pre-split bf16 planes (APh/APl), straight 16B copies.
// OMODE 0: fp32 -> Out; 1: bf16 planes [s][64] scaled; 2: transposed planes.
// ---------------------------------------------------------------------------
constexpr int LDS_PAD = 72;
constexpr int GEMM_SMEM = (128 * LDS_PAD * 2 + 64 * LDS_PAD * 2) * 2;  // 55296

template <bool A_PLANES, int OMODE>
__device__ __forceinline__ void gemm_128x64_split(
    const float* __restrict__ A, 
    const __nv_bfloat16* __restrict__ APh,
    const __nv_bfloat16* __restrict__ APl,
    int ldA,
    const __nv_bfloat16* __restrict__ Bh_g,
    const __nv_bfloat16* __restrict__ Bl_g,
    const float* __restrict__ bias,
    float* __restrict__ Out, int ldOut,
    char* smem,
    float fold,
    __nv_bfloat16* __restrict__ Oh, __nv_bfloat16* __restrict__ Ol,
    int sOff)
{
    __nv_bfloat16* As_hi = reinterpret_cast<__nv_bfloat16*>(smem);
    __nv_bfloat16* As_lo = As_hi + 128 * LDS_PAD;
    __nv_bfloat16* Bs_hi = As_lo + 128 * LDS_PAD;
    __nv_bfloat16* Bs_lo = Bs_hi + 64 * LDS_PAD;

    const int tid  = threadIdx.x;
    const int wid  = tid >> 5;
    const int lane = tid & 31;
    const int g    = lane >> 2;
    const int t    = lane & 3;
    const int m0   = (wid >> 1) * 32;
    const int n0w  = (wid & 1) * 32;

    float acc[2][4][4];
    #pragma unroll
    for (int mf = 0; mf < 2; mf++)
        #pragma unroll
        for (int nf = 0; nf < 4; nf++)
            #pragma unroll
            for (int r = 0; r < 4; r++) acc[mf][nf][r] = 0.f;

    for (int c = 0; c < 8; c++) {
        const int kk = c * 64;

        if (!A_PLANES) {
            #pragma unroll
            for (int i = 0; i < 8; i++) {
                int idx = tid + i * 256;
                int row = idx >> 4, c4 = idx & 15;
                float4 v = *reinterpret_cast<const float4*>(A + (size_t)row * ldA + kk + c4 * 4);
                __nv_bfloat16 h0 = __float2bfloat16(v.x);
                __nv_bfloat16 h1 = __float2bfloat16(v.y);
                __nv_bfloat16 h2 = __float2bfloat16(v.z);
                __nv_bfloat16 h3 = __float2bfloat16(v.w);
                __nv_bfloat16 l0 = __float2bfloat16(v.x - __bfloat162float(h0));
                __nv_bfloat16 l1 = __float2bfloat16(v.y - __bfloat162float(h1));
                __nv_bfloat16 l2 = __float2bfloat16(v.z - __bfloat162float(h2));
                __nv_bfloat16 l3 = __float2bfloat16(v.w - __bfloat162float(h3));
                __nv_bfloat162 hp0 = __halves2bfloat162(h0, h1);
                __nv_bfloat162 hp1 = __halves2bfloat162(h2, h3);
                __nv_bfloat162 lp0 = __halves2bfloat162(l0, l1);
                __nv_bfloat162 lp1 = __halves2bfloat162(l2, l3);
                uint2 hw = make_uint2(*reinterpret_cast<uint32_t*>(&hp0),
                                      *reinterpret_cast<uint32_t*>(&hp1));
                uint2 lw = make_uint2(*reinterpret_cast<uint32_t*>(&lp0),
                                      *reinterpret_cast<uint32_t*>(&lp1));
                *reinterpret_cast<uint2*>(As_hi + row * LDS_PAD + c4 * 4) = hw;
                *reinterpret_cast<uint2*>(As_lo + row * LDS_PAD + c4 * 4) = lw;
            }
        } else {
            #pragma unroll
            for (int i = 0; i < 4; i++) {
                int idx = tid + i * 256;          // 0..1023, 128 rows x 8 groups
                int row = idx >> 3, cq = (idx & 7) * 8;
                *reinterpret_cast<uint4*>(As_hi + row * LDS_PAD + cq) =
                    *reinterpret_cast<const uint4*>(APh + (size_t)row * ldA + kk + cq);
                *reinterpret_cast<uint4*>(As_lo + row * LDS_PAD + cq) =
                    *reinterpret_cast<const uint4*>(APl + (size_t)row * ldA + kk + cq);
            }
        }

        #pragma unroll
        for (int i = 0; i < 2; i++) {
            int idx = tid + i * 256;
            int n = idx >> 3, q = idx & 7;
            *reinterpret_cast<uint4*>(Bs_hi + n * LDS_PAD + q * 8) =
                *reinterpret_cast<const uint4*>(Bh_g + (size_t)n * 512 + kk + q * 8);
            *reinterpret_cast<uint4*>(Bs_lo + n * LDS_PAD + q * 8) =
                *reinterpret_cast<const uint4*>(Bl_g + (size_t)n * 512 + kk + q * 8);
        }
        __syncthreads();

        #pragma unroll
        for (int ks = 0; ks < 4; ks++) {
            uint32_t ah[2][4], al[2][4];
            #pragma unroll
            for (int mf = 0; mf < 2; mf++) {
                int base = (m0 + mf * 16 + g) * LDS_PAD + ks * 16 + t * 2;
                ah[mf][0] = *reinterpret_cast<const uint32_t*>(As_hi + base);
                ah[mf][1] = *reinterpret_cast<const uint32_t*>(As_hi + base + 8 * LDS_PAD);
                ah[mf][2] = *reinterpret_cast<const uint32_t*>(As_hi + base + 8);
                ah[mf][3] = *reinterpret_cast<const uint32_t*>(As_hi + base + 8 * LDS_PAD + 8);
                al[mf][0] = *reinterpret_cast<const uint32_t*>(As_lo + base);
                al[mf][1] = *reinterpret_cast<const uint32_t*>(As_lo + base + 8 * LDS_PAD);
                al[mf][2] = *reinterpret_cast<const uint32_t*>(As_lo + base + 8);
                al[mf][3] = *reinterpret_cast<const uint32_t*>(As_lo + base + 8 * LDS_PAD + 8);
            }
            uint32_t bh[4][2], bl[4][2];
            #pragma unroll
            for (int nf = 0; nf < 4; nf++) {
                int base = (n0w + nf * 8 + g) * LDS_PAD + ks * 16 + t * 2;
                bh[nf][0] = *reinterpret_cast<const uint32_t*>(Bs_hi + base);
                bh[nf][1] = *reinterpret_cast<const uint32_t*>(Bs_hi + base + 8);
                bl[nf][0] = *reinterpret_cast<const uint32_t*>(Bs_lo + base);
                bl[nf][1] = *reinterpret_cast<const uint32_t*>(Bs_lo + base + 8);
            }
            #pragma unroll
            for (int mf = 0; mf < 2; mf++)
                #pragma unroll
                for (int nf = 0; nf < 4; nf++) {
                    mma_bf16(acc[mf][nf], ah[mf], bh[nf]);
                    mma_bf16(acc[mf][nf], ah[mf], bl[nf]);
                    mma_bf16(acc[mf][nf], al[mf], bh[nf]);
                }
        }
        __syncthreads();
    }

    // ---- epilogue ----
    #pragma unroll
    for (int mf = 0; mf < 2; mf++) {
        #pragma unroll
        for (int nf = 0; nf < 4; nf++) {
            int row = m0 + mf * 16 + g;
            int col = n0w + nf * 8 + t * 2;
            float b0 = bias[col], b1 = bias[col + 1];
            float v00 = acc[mf][nf][0] + b0, v01 = acc[mf][nf][1] + b1;
            float v10 = acc[mf][nf][2] + b0, v11 = acc[mf][nf][3] + b1;
            if (OMODE == 0) {
                *reinterpret_cast<float2*>(Out + (size_t)row * ldOut + col) =
                    make_float2(v00, v01);
                *reinterpret_cast<float2*>(Out + (size_t)(row + 8) * ldOut + col) =
                    make_float2(v10, v11);
            } else if (OMODE == 1) {
                v00 *= fold; v01 *= fold; v10 *= fold; v11 *= fold;
                uint32_t lo0, lo1;
                uint32_t hi0 = pack_bf16x2(v00, v01, lo0);
                uint32_t hi1 = pack_bf16x2(v10, v11, lo1);
                *reinterpret_cast<uint32_t*>(Oh + (size_t)row * 64 + col) = hi0;
                *reinterpret_cast<uint32_t*>(Ol + (size_t)row * 64 + col) = lo0;
                *reinterpret_cast<uint32_t*>(Oh + (size_t)(row + 8) * 64 + col) = hi1;
                *reinterpret_cast<uint32_t*>(Ol + (size_t)(row + 8) * 64 + col) = lo1;
            } else {
                float vv[4] = {v00, v01, v10, v11};
                int rr[4] = {row, row, row + 8, row + 8};
                int cc[4] = {col, col + 1, col, col + 1};
                #pragma unroll
                for (int q = 0; q < 4; q++) {
                    __nv_bfloat16 hi = __float2bfloat16(vv[q]);
                    __nv_bfloat16 lo = __float2bfloat16(vv[q] - __bfloat162float(hi));
                    size_t a = (size_t)cc[q] * S + sOff + rr[q];
                    Oh[a] = hi;
                    Ol[a] = lo;
                }
            }
        }
    }
}

// ---------------------------------------------------------------------------
// QKV projection: grid (S/128, B*H, 3), block 256
// ---------------------------------------------------------------------------
__global__ void __launch_bounds__(256)
proj_mma(const float* __restrict__ Q, const float* __restrict__ K,
         const float* __restrict__ V,
         const float* __restrict__ bq, const float* __restrict__ bk,
         const float* __restrict__ bv)
{
    extern __shared__ char smem[];
    const int p  = blockIdx.z;
    const int bh = blockIdx.y;
    const int b  = bh >> 3, h = bh & 7;
    const int s0 = blockIdx.x * 128;

    const float* In   = (p == 0) ? Q : (p == 1) ? K : V;
    const float* bias = ((p == 0) ? bq : (p == 1) ? bk : bv) + h * DH;
    const size_t hb = (size_t)bh * S * DH;

    const float* Ab = In + ((size_t)b * S + s0) * D;
    const __nv_bfloat16* Wh = g_Wt_hi + (size_t)(p * H + h) * DH * D;
    const __nv_bfloat16* Wl = g_Wt_lo + (size_t)(p * H + h) * DH * D;

    if (p == 0) {
        gemm_128x64_split<false, 1>(Ab, nullptr, nullptr, D, Wh, Wl, bias,
                                    nullptr, 0, smem, FOLD_F,
                                    g_Qbh + hb + (size_t)s0 * 64,
                                    g_Qbl + hb + (size_t)s0 * 64, 0);
    } else if (p == 1) {
        gemm_128x64_split<false, 1>(Ab, nullptr, nullptr, D, Wh, Wl, bias,
                                    nullptr, 0, smem, 1.0f,
                                    g_Kbh + hb + (size_t)s0 * 64,
                                    g_Kbl + hb + (size_t)s0 * 64, 0);
    } else {
        gemm_128x64_split<false, 2>(Ab, nullptr, nullptr, D, Wh, Wl, bias,
                                    nullptr, 0, smem, 1.0f,
                                    g_Vth + hb, g_Vtl + hb, s0);
    }
}

// ---------------------------------------------------------------------------
// Output projection: grid (512/64, 1024/128, B), block 256. A from X planes.
// ---------------------------------------------------------------------------
__global__ void __launch_bounds__(256)
oproj_mma(const float* __restrict__ bo, float* __restrict__ out)
{
    extern __shared__ char smem[];
    const int b  = blockIdx.z;
    const int m0 = blockIdx.y * 128;
    const int n0 = blockIdx.x * 64;

    gemm_128x64_split<true, 0>(nullptr,
                               g_Xh + (size_t)b * 1024 * 512 + (size_t)m0 * 512,
                               g_Xl + (size_t)b * 1024 * 512 + (size_t)m0 * 512,
                               512,
                               g_Wot_hi + (size_t)n0 * D,
                               g_Wot_lo + (size_t)n0 * D,
                               bo + n0,
                               out + (size_t)b * 1024 * 512 + (size_t)m0 * 512 + n0,
                               512, smem, 1.0f, nullptr, nullptr, 0);
}

// ---------------------------------------------------------------------------
// Flash attention, KV tile = 32 (smaller smem -> 4 blocks/SM target).
// grid (16, 64), block 128 (4 warps, 16 q rows each).
// smem per buffer: Kh[32][72], Kl[32][72], Vh[64][40], Vl[64][40]
// ---------------------------------------------------------------------------
constexpr int KPAD    = 72;
constexpr int VPAD    = 40;
constexpr int PLANE_K = 32 * KPAD;                  // 2304 elems
constexpr int PLANE_V = 64 * VPAD;                  // 2560 elems
constexpr int ABUF2   = 2 * PLANE_K + 2 * PLANE_V;  // 9728 elems
constexpr int ATTN_SMEM = 2 * ABUF2 * 2;            // 38912 B

__device__ __forceinline__ void attn_issue_tile32(
    const __nv_bfloat16* Khp, const __nv_bfloat16* Klp,
    const __nv_bfloat16* Vhp, const __nv_bfloat16* Vlp,
    uint32_t sbuf, int kv0, int tid)
{
    #pragma unroll
    for (int i = 0; i < 2; i++) {
        int slot = tid + i * 128;               // 0..255
        int rK = slot >> 3, cK = (slot & 7) * 8;
        CP_ASYNC16(sbuf + (uint32_t)(rK * KPAD + cK) * 2,
                   Khp + (size_t)(kv0 + rK) * 64 + cK);
        CP_ASYNC16(sbuf + (uint32_t)(PLANE_K + rK * KPAD + cK) * 2,
                   Klp + (size_t)(kv0 + rK) * 64 + cK);
        int rV = slot >> 2, cV = (slot & 3) * 8;
        CP_ASYNC16(sbuf + (uint32_t)(2 * PLANE_K + rV * VPAD + cV) * 2,
                   Vhp + (size_t)rV * S + kv0 + cV);
        CP_ASYNC16(sbuf + (uint32_t)(2 * PLANE_K + PLANE_V + rV * VPAD + cV) * 2,
                   Vlp + (size_t)rV * S + kv0 + cV);
    }
    CP_ASYNC_COMMIT();
}

__global__ void __launch_bounds__(128, 4) attn_mma()
{
    extern __shared__ __nv_bfloat16 smatt[];
    const int tid  = threadIdx.x;
    const int w    = tid >> 5;
    const int lane = tid & 31;
    const int g    = lane >> 2;
    const int t    = lane & 3;
    const int bh   = blockIdx.y;
    const int q0   = blockIdx.x * 64;
    const size_t hb = (size_t)bh * S * DH;

    const __nv_bfloat16* Qhp = g_Qbh + hb;
    const __nv_bfloat16* Qlp = g_Qbl + hb;
    const __nv_bfloat16* Khp = g_Kbh + hb;
    const __nv_bfloat16* Klp = g_Kbl + hb;
    const __nv_bfloat16* Vhp = g_Vth + hb;
    const __nv_bfloat16* Vlp = g_Vtl + hb;
    const uint32_t sbase = (uint32_t)__cvta_generic_to_shared(smatt);

    // Q fragments, register-resident (scale*log2e folded)
    uint32_t qh[4][4], ql[4][4];
    const int r0 = q0 + w * 16 + g;
    #pragma unroll
    for (int ks = 0; ks < 4; ks++) {
        int c0 = ks * 16 + 2 * t;
        qh[ks][0] = *reinterpret_cast<const uint32_t*>(Qhp + (size_t)r0 * 64 + c0);
        qh[ks][1] = *reinterpret_cast<const uint32_t*>(Qhp + (size_t)(r0 + 8) * 64 + c0);
        qh[ks][2] = *reinterpret_cast<const uint32_t*>(Qhp + (size_t)r0 * 64 + c0 + 8);
        qh[ks][3] = *reinterpret_cast<const uint32_t*>(Qhp + (size_t)(r0 + 8) * 64 + c0 + 8);
        ql[ks][0] = *reinterpret_cast<const uint32_t*>(Qlp + (size_t)r0 * 64 + c0);
        ql[ks][1] = *reinterpret_cast<const uint32_t*>(Qlp + (size_t)(r0 + 8) * 64 + c0);
        ql[ks][2] = *reinterpret_cast<const uint32_t*>(Qlp + (size_t)r0 * 64 + c0 + 8);
        ql[ks][3] = *reinterpret_cast<const uint32_t*>(Qlp + (size_t)(r0 + 8) * 64 + c0 + 8);
    }

    float O[8][4];
    #pragma unroll
    for (int nf = 0; nf < 8; nf++)
        #pragma unroll
        for (int r = 0; r < 4; r++) O[nf][r] = 0.f;
    float ma = -INFINITY, mb = -INFINITY, la = 0.f, lb = 0.f;

    attn_issue_tile32(Khp, Klp, Vhp, Vlp, sbase, 0, tid);

    for (int kt = 0; kt < 32; kt++) {
        const int bb = kt & 1;
        if (kt + 1 < 32) {
            attn_issue_tile32(Khp, Klp, Vhp, Vlp,
                              sbase + (uint32_t)(1 - bb) * ABUF2 * 2,
                              (kt + 1) * 32, tid);
            CP_ASYNC_WAIT(1);
        } else {
            CP_ASYNC_WAIT(0);
        }
        __syncthreads();

        const __nv_bfloat16* sb = smatt + bb * ABUF2;

        // ---- scores: 16 q x 32 kv (base-2 domain) ----
        float sc[4][4];
        #pragma unroll
        for (int nf = 0; nf < 4; nf++)
            #pragma unroll
            for (int r = 0; r < 4; r++) sc[nf][r] = 0.f;

        #pragma unroll
        for (int ks = 0; ks < 4; ks++) {
            #pragma unroll
            for (int nf = 0; nf < 4; nf++) {
                int base = (nf * 8 + g) * KPAD + ks * 16 + 2 * t;
                uint32_t kh[2], kl[2];
                kh[0] = *reinterpret_cast<const uint32_t*>(sb + base);
                kh[1] = *reinterpret_cast<const uint32_t*>(sb + base + 8);
                kl[0] = *reinterpret_cast<const uint32_t*>(sb + PLANE_K + base);
                kl[1] = *reinterpret_cast<const uint32_t*>(sb + PLANE_K + base + 8);
                mma_bf16(sc[nf], qh[ks], kh);
                mma_bf16(sc[nf], qh[ks], kl);
                mma_bf16(sc[nf], ql[ks], kh);
            }
        }

        // ---- online softmax ----
        float mxa = sc[0][0], mxb = sc[0][2];
        #pragma unroll
        for (int nf = 0; nf < 4; nf++) {
            mxa = fmaxf(mxa, fmaxf(sc[nf][0], sc[nf][1]));
            mxb = fmaxf(mxb, fmaxf(sc[nf][2], sc[nf][3]));
        }
        mxa = fmaxf(mxa, __shfl_xor_sync(0xffffffffu, mxa, 1));
        mxa = fmaxf(mxa, __shfl_xor_sync(0xffffffffu, mxa, 2));
        mxb = fmaxf(mxb, __shfl_xor_sync(0xffffffffu, mxb, 1));
        mxb = fmaxf(mxb, __shfl_xor_sync(0xffffffffu, mxb, 2));
        float mna = fmaxf(ma, mxa), mnb = fmaxf(mb, mxb);
        float aa = ex2f(ma - mna), ab = ex2f(mb - mnb);
        ma = mna; mb = mnb;
        float rsa = 0.f, rsb = 0.f;
        #pragma unroll
        for (int nf = 0; nf < 4; nf++) {
            sc[nf][0] = ex2f(sc[nf][0] - mna);
            sc[nf][1] = ex2f(sc[nf][1] - mna);
            sc[nf][2] = ex2f(sc[nf][2] - mnb);
            sc[nf][3] = ex2f(sc[nf][3] - mnb);
            rsa += sc[nf][0] + sc[nf][1];
            rsb += sc[nf][2] + sc[nf][3];
        }
        rsa += __shfl_xor_sync(0xffffffffu, rsa, 1);
        rsa += __shfl_xor_sync(0xffffffffu, rsa, 2);
        rsb += __shfl_xor_sync(0xffffffffu, rsb, 1);
        rsb += __shfl_xor_sync(0xffffffffu, rsb, 2);
        la = la * aa + rsa;
        lb = lb * ab + rsb;
        #pragma unroll
        for (int nf = 0; nf < 8; nf++) {
            O[nf][0] *= aa; O[nf][1] *= aa;
            O[nf][2] *= ab; O[nf][3] *= ab;
        }

        // ---- P @ V : k-dim = 32 kv (2 k-steps) ----
        #pragma unroll
        for (int ks2 = 0; ks2 < 2; ks2++) {
            uint32_t ph[4], pl[4];
            ph[0] = pack_bf16x2(sc[2 * ks2][0],     sc[2 * ks2][1],     pl[0]);
            ph[1] = pack_bf16x2(sc[2 * ks2][2],     sc[2 * ks2][3],     pl[1]);
            ph[2] = pack_bf16x2(sc[2 * ks2 + 1][0], sc[2 * ks2 + 1][1], pl[2]);
            ph[3] = pack_bf16x2(sc[2 * ks2 + 1][2], sc[2 * ks2 + 1][3], pl[3]);

            #pragma unroll
            for (int nf = 0; nf < 8; nf++) {
                int base = 2 * PLANE_K + (nf * 8 + g) * VPAD + ks2 * 16 + 2 * t;
                uint32_t vh[2], vl[2];
                vh[0] = *reinterpret_cast<const uint32_t*>(sb + base);
                vh[1] = *reinterpret_cast<const uint32_t*>(sb + base + 8);
                vl[0] = *reinterpret_cast<const uint32_t*>(sb + PLANE_V + base);
                vl[1] = *reinterpret_cast<const uint32_t*>(sb + PLANE_V + base + 8);
                mma_bf16(O[nf], ph, vh);
                mma_bf16(O[nf], ph, vl);
                mma_bf16(O[nf], pl, vh);
            }
        }
        __syncthreads();
    }

    // ---- epilogue: X bf16 hi/lo planes ----
    float ia = 1.0f / la, ib = 1.0f / lb;
    #pragma unroll
    for (int nf = 0; nf < 8; nf++) {
        int c = nf * 8 + 2 * t;
        size_t a0 = hb + (size_t)r0 * 64 + c;
        size_t a1 = hb + (size_t)(r0 + 8) * 64 + c;
        uint32_t lo0, lo1;
        uint32_t hi0 = pack_bf16x2(O[nf][0] * ia, O[nf][1] * ia, lo0);
        uint32_t hi1 = pack_bf16x2(O[nf][2] * ib, O[nf][3] * ib, lo1);
        *reinterpret_cast<uint32_t*>(g_Xh + a0) = hi0;
        *reinterpret_cast<uint32_t*>(g_Xl + a0) = lo0;
        *reinterpret_cast<uint32_t*>(g_Xh + a1) = hi1;
        *reinterpret_cast<uint32_t*>(g_Xl + a1) = lo1;
    }
}

// ---------------------------------------------------------------------------
extern "C" void kernel_launch(void* const* d_in, const int* in_sizes, int n_in,
                              void* d_out, int out_size)
{
    const float* Q  = (const float*)d_in[0];
    const float* K  = (const float*)d_in[1];
    const float* V  = (const float*)d_in[2];
    const float* Wq = (const float*)d_in[3];
    const float* bq = (const float*)d_in[4];
    const float* Wk = (const float*)d_in[5];
    const float* bk = (const float*)d_in[6];
    const float* Wv = (const float*)d_in[7];
    const float* bv = (const float*)d_in[8];
    const float* Wo = (const float*)d_in[9];
    const float* bo = (const float*)d_in[10];
    float* out = (float*)d_out;

    // 0) weight transpose + bf16 split
    prep_weights<<<4096, 256>>>(Wq, Wk, Wv, Wo);

    // 1) QKV projections -> bf16 hi/lo planes
    cudaFuncSetAttribute(proj_mma, cudaFuncAttributeMaxDynamicSharedMemorySize, GEMM_SMEM);
    proj_mma<<<dim3(S / 128, B * H, 3), 256, GEMM_SMEM>>>(Q, K, V, bq, bk, bv);

    // 2) attention (KV tile 32, 4 blocks/SM target)
    cudaFuncSetAttribute(attn_mma, cudaFuncAttributeMaxDynamicSharedMemorySize, ATTN_SMEM);
    attn_mma<<<dim3(S / 64, B * H), 128, ATTN_SMEM>>>();

    // 3) output projection from X planes
    cudaFuncSetAttribute(oproj_mma, cudaFuncAttributeMaxDynamicSharedMemorySize, GEMM_SMEM);
    oproj_mma<<<dim3(512 / 64, 1024 / 128, B), 256, GEMM_SMEM>>>(bo, out);
}

// round 7
// speedup vs baseline: 1.1102x; 1.0786x over previous
#include <cuda_runtime.h>
#include <cuda_bf16.h>
#include <math.h>
#include <stdint.h>

// ---------------------------------------------------------------------------
// Problem constants
// ---------------------------------------------------------------------------
constexpr int B  = 8;
constexpr int S  = 1024;
constexpr int D  = 512;
constexpr int H  = 8;
constexpr int DH = 64;
constexpr int BHSD = B * H * S * DH;

// softmax scale folded into Q planes, base-2 domain: 1/sqrt(64) * log2(e)
#define FOLD_F 0.18033688011112042f

// ---------------------------------------------------------------------------
// Device scratch
// ---------------------------------------------------------------------------
__device__ __nv_bfloat16 g_Qbh[BHSD], g_Qbl[BHSD];   // [bh][s][dh], scale folded
__device__ __nv_bfloat16 g_Kbh[BHSD], g_Kbl[BHSD];   // [bh][s][dh]
__device__ __nv_bfloat16 g_Vth[BHSD], g_Vtl[BHSD];   // [bh][dh][s]  (transposed)
__device__ __nv_bfloat16 g_Xh [BHSD], g_Xl [BHSD];   // attn out planes [bh][s][dh]

// Pre-transposed, bf16-split weight planes: [n][k] (k contiguous, ld=512)
__device__ __nv_bfloat16 g_Wt_hi [3 * H * DH * D];
__device__ __nv_bfloat16 g_Wt_lo [3 * H * DH * D];
__device__ __nv_bfloat16 g_Wot_hi[D * D];
__device__ __nv_bfloat16 g_Wot_lo[D * D];

// ---------------------------------------------------------------------------
// helpers
// ---------------------------------------------------------------------------
__device__ __forceinline__ void mma_bf16(float* d, const uint32_t* a, const uint32_t* b) {
    asm volatile(
        "mma.sync.aligned.m16n8k16.row.col.f32.bf16.bf16.f32 "
        "{%0,%1,%2,%3}, {%4,%5,%6,%7}, {%8,%9}, {%0,%1,%2,%3};"
        : "+f"(d[0]), "+f"(d[1]), "+f"(d[2]), "+f"(d[3])
        : "r"(a[0]), "r"(a[1]), "r"(a[2]), "r"(a[3]), "r"(b[0]), "r"(b[1]));
}

__device__ __forceinline__ void ldsm4(uint32_t* r, uint32_t addr) {
    asm volatile("ldmatrix.sync.aligned.m8n8.x4.shared.b16 {%0,%1,%2,%3}, [%4];"
        : "=r"(r[0]), "=r"(r[1]), "=r"(r[2]), "=r"(r[3]) : "r"(addr));
}

__device__ __forceinline__ float ex2f(float x) {
    float r;
    asm("ex2.approx.f32 %0, %1;" : "=f"(r) : "f"(x));
    return r;
}

#define CP_ASYNC16(dst_u32, gptr) \
    asm volatile("cp.async.cg.shared.global [%0], [%1], 16;" :: "r"(dst_u32), "l"(gptr))
#define CP_ASYNC_COMMIT() asm volatile("cp.async.commit_group;" ::: "memory")
#define CP_ASYNC_WAIT(n)  asm volatile("cp.async.wait_group %0;" :: "n"(n) : "memory")

__device__ __forceinline__ uint32_t pack_bf16x2(float a, float b, uint32_t& lo) {
    __nv_bfloat162 h = __floats2bfloat162_rn(a, b);
    float2 bk = __bfloat1622float2(h);
    __nv_bfloat162 l = __floats2bfloat162_rn(a - bk.x, b - bk.y);
    lo = *reinterpret_cast<uint32_t*>(&l);
    return *reinterpret_cast<uint32_t*>(&h);
}

// ---------------------------------------------------------------------------
// Weight prep: transpose + bf16 split
// ---------------------------------------------------------------------------
__global__ void prep_weights(const float* __restrict__ Wq,
                             const float* __restrict__ Wk,
                             const float* __restrict__ Wv,
                             const float* __restrict__ Wo)
{
    int idx = blockIdx.x * blockDim.x + threadIdx.x;   // 0 .. 1048575
    if (idx < 3 * H * DH * D) {
        int k = idx & 511;
        int e = (idx >> 9) & 63;
        int h = (idx >> 15) & 7;
        int p = idx >> 18;
        const float* W = (p == 0) ? Wq : (p == 1) ? Wk : Wv;
        float v = W[h * (D * DH) + k * DH + e];
        __nv_bfloat16 hi = __float2bfloat16(v);
        __nv_bfloat16 lo = __float2bfloat16(v - __bfloat162float(hi));
        g_Wt_hi[idx] = hi;
        g_Wt_lo[idx] = lo;
    } else {
        int j = idx - 3 * H * DH * D;
        int k = j & 511;
        int n = j >> 9;
        float v = Wo[k * 512 + n];
        __nv_bfloat16 hi = __float2bfloat16(v);
        __nv_bfloat16 lo = __float2bfloat16(v - __bfloat162float(hi));
        g_Wot_hi[j] = hi;
        g_Wot_lo[j] = lo;
    }
}

// ---------------------------------------------------------------------------
// GEMM body: Out[128,64] = A[128,512] * B[64,512]^T + bias (R4-proven shape)
// Fragments via ldmatrix. OMODE 0: fp32 out; 1: bf16 planes; 2: transposed.
// ---------------------------------------------------------------------------
constexpr int LDS_PAD = 72;
constexpr int GEMM_SMEM = (128 * LDS_PAD * 2 + 64 * LDS_PAD * 2) * 2;  // 55296
constexpr uint32_t GA_LO = 128 * LDS_PAD * 2;            // As_lo byte offset
constexpr uint32_t GB_HI = 2 * 128 * LDS_PAD * 2;        // Bs_hi
constexpr uint32_t GB_LO = GB_HI + 64 * LDS_PAD * 2;     // Bs_lo

template <bool A_PLANES, int OMODE>
__device__ __forceinline__ void gemm_128x64_split(
    const float* __restrict__ A,
    const __nv_bfloat16* __restrict__ APh,
    const __nv_bfloat16* __restrict__ APl,
    int ldA,
    const __nv_bfloat16* __restrict__ Bh_g,
    const __nv_bfloat16* __restrict__ Bl_g,
    const float* __restrict__ bias,
    float* __restrict__ Out, int ldOut,
    char* smem,
    float fold,
    __nv_bfloat16* __restrict__ Oh, __nv_bfloat16* __restrict__ Ol,
    int sOff)
{
    __nv_bfloat16* As_hi = reinterpret_cast<__nv_bfloat16*>(smem);
    __nv_bfloat16* As_lo = As_hi + 128 * LDS_PAD;
    __nv_bfloat16* Bs_hi = As_lo + 128 * LDS_PAD;
    __nv_bfloat16* Bs_lo = Bs_hi + 64 * LDS_PAD;

    const int tid  = threadIdx.x;
    const int wid  = tid >> 5;
    const int lane = tid & 31;
    const int g    = lane >> 2;
    const int t    = lane & 3;
    const int m0   = (wid >> 1) * 32;
    const int n0w  = (wid & 1) * 32;

    const uint32_t su = (uint32_t)__cvta_generic_to_shared(smem);
    // ldmatrix lane->row/col selects: A uses bit3->row+8, bit4->col+8;
    // B uses bit4->row+8, bit3->col+8 (matches m16n8k16 fragment order).
    const int laneRA = (lane & 7) + ((lane >> 3) & 1) * 8;
    const int laneCA = ((lane >> 4) & 1) * 8;
    const int laneRB = (lane & 7) + ((lane >> 4) & 1) * 8;
    const int laneCB = ((lane >> 3) & 1) * 8;
    uint32_t aoff[2], boff[2];
    #pragma unroll
    for (int mf = 0; mf < 2; mf++)
        aoff[mf] = (uint32_t)((m0 + mf * 16 + laneRA) * LDS_PAD + laneCA) * 2;
    #pragma unroll
    for (int nfp = 0; nfp < 2; nfp++)
        boff[nfp] = (uint32_t)((n0w + nfp * 16 + laneRB) * LDS_PAD + laneCB) * 2;

    float acc[2][4][4];
    #pragma unroll
    for (int mf = 0; mf < 2; mf++)
        #pragma unroll
        for (int nf = 0; nf < 4; nf++)
            #pragma unroll
            for (int r = 0; r < 4; r++) acc[mf][nf][r] = 0.f;

    for (int c = 0; c < 8; c++) {
        const int kk = c * 64;

        if (!A_PLANES) {
            #pragma unroll
            for (int i = 0; i < 8; i++) {
                int idx = tid + i * 256;
                int row = idx >> 4, c4 = idx & 15;
                float4 v = *reinterpret_cast<const float4*>(A + (size_t)row * ldA + kk + c4 * 4);
                __nv_bfloat16 h0 = __float2bfloat16(v.x);
                __nv_bfloat16 h1 = __float2bfloat16(v.y);
                __nv_bfloat16 h2 = __float2bfloat16(v.z);
                __nv_bfloat16 h3 = __float2bfloat16(v.w);
                __nv_bfloat16 l0 = __float2bfloat16(v.x - __bfloat162float(h0));
                __nv_bfloat16 l1 = __float2bfloat16(v.y - __bfloat162float(h1));
                __nv_bfloat16 l2 = __float2bfloat16(v.z - __bfloat162float(h2));
                __nv_bfloat16 l3 = __float2bfloat16(v.w - __bfloat162float(h3));
                __nv_bfloat162 hp0 = __halves2bfloat162(h0, h1);
                __nv_bfloat162 hp1 = __halves2bfloat162(h2, h3);
                __nv_bfloat162 lp0 = __halves2bfloat162(l0, l1);
                __nv_bfloat162 lp1 = __halves2bfloat162(l2, l3);
                uint2 hw = make_uint2(*reinterpret_cast<uint32_t*>(&hp0),
                                      *reinterpret_cast<uint32_t*>(&hp1));
                uint2 lw = make_uint2(*reinterpret_cast<uint32_t*>(&lp0),
                                      *reinterpret_cast<uint32_t*>(&lp1));
                *reinterpret_cast<uint2*>(As_hi + row * LDS_PAD + c4 * 4) = hw;
                *reinterpret_cast<uint2*>(As_lo + row * LDS_PAD + c4 * 4) = lw;
            }
        } else {
            #pragma unroll
            for (int i = 0; i < 4; i++) {
                int idx = tid + i * 256;
                int row = idx >> 3, cq = (idx & 7) * 8;
                *reinterpret_cast<uint4*>(As_hi + row * LDS_PAD + cq) =
                    *reinterpret_cast<const uint4*>(APh + (size_t)row * ldA + kk + cq);
                *reinterpret_cast<uint4*>(As_lo + row * LDS_PAD + cq) =
                    *reinterpret_cast<const uint4*>(APl + (size_t)row * ldA + kk + cq);
            }
        }

        #pragma unroll
        for (int i = 0; i < 2; i++) {
            int idx = tid + i * 256;
            int n = idx >> 3, q = idx & 7;
            *reinterpret_cast<uint4*>(Bs_hi + n * LDS_PAD + q * 8) =
                *reinterpret_cast<const uint4*>(Bh_g + (size_t)n * 512 + kk + q * 8);
            *reinterpret_cast<uint4*>(Bs_lo + n * LDS_PAD + q * 8) =
                *reinterpret_cast<const uint4*>(Bl_g + (size_t)n * 512 + kk + q * 8);
        }
        __syncthreads();

        #pragma unroll
        for (int ks = 0; ks < 4; ks++) {
            const uint32_t kb = (uint32_t)ks * 32;
            uint32_t ah[2][4], al[2][4];
            #pragma unroll
            for (int mf = 0; mf < 2; mf++) {
                ldsm4(ah[mf], su + aoff[mf] + kb);
                ldsm4(al[mf], su + GA_LO + aoff[mf] + kb);
            }
            #pragma unroll
            for (int nfp = 0; nfp < 2; nfp++) {
                uint32_t bh4[4], bl4[4];
                ldsm4(bh4, su + GB_HI + boff[nfp] + kb);
                ldsm4(bl4, su + GB_LO + boff[nfp] + kb);
                #pragma unroll
                for (int j = 0; j < 2; j++) {
                    const int nf = 2 * nfp + j;
                    #pragma unroll
                    for (int mf = 0; mf < 2; mf++) {
                        mma_bf16(acc[mf][nf], ah[mf], bh4 + 2 * j);
                        mma_bf16(acc[mf][nf], ah[mf], bl4 + 2 * j);
                        mma_bf16(acc[mf][nf], al[mf], bh4 + 2 * j);
                    }
                }
            }
        }
        __syncthreads();
    }

    // ---- epilogue ----
    #pragma unroll
    for (int mf = 0; mf < 2; mf++) {
        #pragma unroll
        for (int nf = 0; nf < 4; nf++) {
            int row = m0 + mf * 16 + g;
            int col = n0w + nf * 8 + t * 2;
            float b0 = bias[col], b1 = bias[col + 1];
            float v00 = acc[mf][nf][0] + b0, v01 = acc[mf][nf][1] + b1;
            float v10 = acc[mf][nf][2] + b0, v11 = acc[mf][nf][3] + b1;
            if (OMODE == 0) {
                *reinterpret_cast<float2*>(Out + (size_t)row * ldOut + col) =
                    make_float2(v00, v01);
                *reinterpret_cast<float2*>(Out + (size_t)(row + 8) * ldOut + col) =
                    make_float2(v10, v11);
            } else if (OMODE == 1) {
                v00 *= fold; v01 *= fold; v10 *= fold; v11 *= fold;
                uint32_t lo0, lo1;
                uint32_t hi0 = pack_bf16x2(v00, v01, lo0);
                uint32_t hi1 = pack_bf16x2(v10, v11, lo1);
                *reinterpret_cast<uint32_t*>(Oh + (size_t)row * 64 + col) = hi0;
                *reinterpret_cast<uint32_t*>(Ol + (size_t)row * 64 + col) = lo0;
                *reinterpret_cast<uint32_t*>(Oh + (size_t)(row + 8) * 64 + col) = hi1;
                *reinterpret_cast<uint32_t*>(Ol + (size_t)(row + 8) * 64 + col) = lo1;
            } else {
                float vv[4] = {v00, v01, v10, v11};
                int rr[4] = {row, row, row + 8, row + 8};
                int cc[4] = {col, col + 1, col, col + 1};
                #pragma unroll
                for (int q = 0; q < 4; q++) {
                    __nv_bfloat16 hi = __float2bfloat16(vv[q]);
                    __nv_bfloat16 lo = __float2bfloat16(vv[q] - __bfloat162float(hi));
                    size_t a = (size_t)cc[q] * S + sOff + rr[q];
                    Oh[a] = hi;
                    Ol[a] = lo;
                }
            }
        }
    }
}

// ---------------------------------------------------------------------------
// QKV projection: grid (S/128, B*H, 3), block 256
// ---------------------------------------------------------------------------
__global__ void __launch_bounds__(256)
proj_mma(const float* __restrict__ Q, const float* __restrict__ K,
         const float* __restrict__ V,
         const float* __restrict__ bq, const float* __restrict__ bk,
         const float* __restrict__ bv)
{
    extern __shared__ char smem[];
    const int p  = blockIdx.z;
    const int bh = blockIdx.y;
    const int b  = bh >> 3, h = bh & 7;
    const int s0 = blockIdx.x * 128;

    const float* In   = (p == 0) ? Q : (p == 1) ? K : V;
    const float* bias = ((p == 0) ? bq : (p == 1) ? bk : bv) + h * DH;
    const size_t hb = (size_t)bh * S * DH;

    const float* Ab = In + ((size_t)b * S + s0) * D;
    const __nv_bfloat16* Wh = g_Wt_hi + (size_t)(p * H + h) * DH * D;
    const __nv_bfloat16* Wl = g_Wt_lo + (size_t)(p * H + h) * DH * D;

    if (p == 0) {
        gemm_128x64_split<false, 1>(Ab, nullptr, nullptr, D, Wh, Wl, bias,
                                    nullptr, 0, smem, FOLD_F,
                                    g_Qbh + hb + (size_t)s0 * 64,
                                    g_Qbl + hb + (size_t)s0 * 64, 0);
    } else if (p == 1) {
        gemm_128x64_split<false, 1>(Ab, nullptr, nullptr, D, Wh, Wl, bias,
                                    nullptr, 0, smem, 1.0f,
                                    g_Kbh + hb + (size_t)s0 * 64,
                                    g_Kbl + hb + (size_t)s0 * 64, 0);
    } else {
        gemm_128x64_split<false, 2>(Ab, nullptr, nullptr, D, Wh, Wl, bias,
                                    nullptr, 0, smem, 1.0f,
                                    g_Vth + hb, g_Vtl + hb, s0);
    }
}

// ---------------------------------------------------------------------------
// Output projection: grid (512/64, 1024/128, B), block 256. A from X planes.
// ---------------------------------------------------------------------------
__global__ void __launch_bounds__(256)
oproj_mma(const float* __restrict__ bo, float* __restrict__ out)
{
    extern __shared__ char smem[];
    const int b  = blockIdx.z;
    const int m0 = blockIdx.y * 128;
    const int n0 = blockIdx.x * 64;

    gemm_128x64_split<true, 0>(nullptr,
                               g_Xh + (size_t)b * 1024 * 512 + (size_t)m0 * 512,
                               g_Xl + (size_t)b * 1024 * 512 + (size_t)m0 * 512,
                               512,
                               g_Wot_hi + (size_t)n0 * D,
                               g_Wot_lo + (size_t)n0 * D,
                               bo + n0,
                               out + (size_t)b * 1024 * 512 + (size_t)m0 * 512 + n0,
                               512, smem, 1.0f, nullptr, nullptr, 0);
}

// ---------------------------------------------------------------------------
// Flash attention (R4 config: KV tile 64, 3 blocks/SM) with ldmatrix feeds.
// grid (16, 64), block 128 (4 warps, 16 Q rows each).
// smem: double-buffered {Kh, Kl, Vh, Vl} tiles of [64][72] bf16.
// ---------------------------------------------------------------------------
constexpr int SPAD  = 72;
constexpr int PLANE = 64 * SPAD;           // elems
constexpr int ABUF  = 4 * PLANE;           // elems per buffer
constexpr int ATTN_SMEM = 2 * ABUF * 2;    // 73728 B

__device__ __forceinline__ void attn_issue_tile(
    const __nv_bfloat16* Khp, const __nv_bfloat16* Klp,
    const __nv_bfloat16* Vhp, const __nv_bfloat16* Vlp,
    uint32_t sbuf, int kv0, int tid)
{
    #pragma unroll
    for (int i = 0; i < 4; i++) {
        int idx = tid + i * 128;           // 0..511
        int row = idx >> 3, c = (idx & 7) * 8;
        uint32_t so = (uint32_t)(row * SPAD + c) * 2;
        CP_ASYNC16(sbuf + so,                 Khp + (size_t)(kv0 + row) * 64 + c);
        CP_ASYNC16(sbuf + PLANE * 2 + so,     Klp + (size_t)(kv0 + row) * 64 + c);
        CP_ASYNC16(sbuf + 2 * PLANE * 2 + so, Vhp + (size_t)row * S + kv0 + c);
        CP_ASYNC16(sbuf + 3 * PLANE * 2 + so, Vlp + (size_t)row * S + kv0 + c);
    }
    CP_ASYNC_COMMIT();
}

__global__ void __launch_bounds__(128, 3) attn_mma()
{
    extern __shared__ __nv_bfloat16 smatt[];
    const int tid  = threadIdx.x;
    const int w    = tid >> 5;
    const int lane = tid & 31;
    const int g    = lane >> 2;
    const int t    = lane & 3;
    const int bh   = blockIdx.y;
    const int q0   = blockIdx.x * 64;
    const size_t hb = (size_t)bh * S * DH;

    const __nv_bfloat16* Qhp = g_Qbh + hb;
    const __nv_bfloat16* Qlp = g_Qbl + hb;
    const __nv_bfloat16* Khp = g_Kbh + hb;
    const __nv_bfloat16* Klp = g_Kbl + hb;
    const __nv_bfloat16* Vhp = g_Vth + hb;
    const __nv_bfloat16* Vlp = g_Vtl + hb;
    const uint32_t sbase = (uint32_t)__cvta_generic_to_shared(smatt);

    // ldmatrix B-operand lane map (bit4 -> row+8, bit3 -> col+8)
    const int laneRB = (lane & 7) + ((lane >> 4) & 1) * 8;
    const int laneCB = ((lane >> 3) & 1) * 8;
    uint32_t fragOff[4];
    #pragma unroll
    for (int nfp = 0; nfp < 4; nfp++)
        fragOff[nfp] = (uint32_t)((nfp * 16 + laneRB) * SPAD + laneCB) * 2;

    // Q fragments, register-resident (scale*log2e folded)
    uint32_t qh[4][4], ql[4][4];
    const int r0 = q0 + w * 16 + g;
    #pragma unroll
    for (int ks = 0; ks < 4; ks++) {
        int c0 = ks * 16 + 2 * t;
        qh[ks][0] = *reinterpret_cast<const uint32_t*>(Qhp + (size_t)r0 * 64 + c0);
        qh[ks][1] = *reinterpret_cast<const uint32_t*>(Qhp + (size_t)(r0 + 8) * 64 + c0);
        qh[ks][2] = *reinterpret_cast<const uint32_t*>(Qhp + (size_t)r0 * 64 + c0 + 8);
        qh[ks][3] = *reinterpret_cast<const uint32_t*>(Qhp + (size_t)(r0 + 8) * 64 + c0 + 8);
        ql[ks][0] = *reinterpret_cast<const uint32_t*>(Qlp + (size_t)r0 * 64 + c0);
        ql[ks][1] = *reinterpret_cast<const uint32_t*>(Qlp + (size_t)(r0 + 8) * 64 + c0);
        ql[ks][2] = *reinterpret_cast<const uint32_t*>(Qlp + (size_t)r0 * 64 + c0 + 8);
        ql[ks][3] = *reinterpret_cast<const uint32_t*>(Qlp + (size_t)(r0 + 8) * 64 + c0 + 8);
    }

    float O[8][4];
    #pragma unroll
    for (int nf = 0; nf < 8; nf++)
        #pragma unroll
        for (int r = 0; r < 4; r++) O[nf][r] = 0.f;
    float ma = -INFINITY, mb = -INFINITY, la = 0.f, lb = 0.f;

    attn_issue_tile(Khp, Klp, Vhp, Vlp, sbase, 0, tid);

    for (int kt = 0; kt < 16; kt++) {
        const int bb = kt & 1;
        if (kt + 1 < 16) {
            attn_issue_tile(Khp, Klp, Vhp, Vlp,
                            sbase + (uint32_t)(1 - bb) * ABUF * 2,
                            (kt + 1) * 64, tid);
            CP_ASYNC_WAIT(1);
        } else {
            CP_ASYNC_WAIT(0);
        }
        __syncthreads();

        const uint32_t sbu = sbase + (uint32_t)bb * ABUF * 2;

        // ---- scores (base-2 domain) ----
        float sc[8][4];
        #pragma unroll
        for (int nf = 0; nf < 8; nf++)
            #pragma unroll
            for (int r = 0; r < 4; r++) sc[nf][r] = 0.f;

        #pragma unroll
        for (int ks = 0; ks < 4; ks++) {
            const uint32_t kb = (uint32_t)ks * 32;
            #pragma unroll
            for (int nfp = 0; nfp < 4; nfp++) {
                uint32_t kh4[4], kl4[4];
                ldsm4(kh4, sbu + fragOff[nfp] + kb);
                ldsm4(kl4, sbu + PLANE * 2 + fragOff[nfp] + kb);
                #pragma unroll
                for (int j = 0; j < 2; j++) {
                    const int nf = 2 * nfp + j;
                    mma_bf16(sc[nf], qh[ks], kh4 + 2 * j);
                    mma_bf16(sc[nf], qh[ks], kl4 + 2 * j);
                    mma_bf16(sc[nf], ql[ks], kh4 + 2 * j);
                }
            }
        }

        // ---- online softmax ----
        float mxa = sc[0][0], mxb = sc[0][2];
        #pragma unroll
        for (int nf = 0; nf < 8; nf++) {
            mxa = fmaxf(mxa, fmaxf(sc[nf][0], sc[nf][1]));
            mxb = fmaxf(mxb, fmaxf(sc[nf][2], sc[nf][3]));
        }
        mxa = fmaxf(mxa, __shfl_xor_sync(0xffffffffu, mxa, 1));
        mxa = fmaxf(mxa, __shfl_xor_sync(0xffffffffu, mxa, 2));
        mxb = fmaxf(mxb, __shfl_xor_sync(0xffffffffu, mxb, 1));
        mxb = fmaxf(mxb, __shfl_xor_sync(0xffffffffu, mxb, 2));
        float mna = fmaxf(ma, mxa), mnb = fmaxf(mb, mxb);
        float aa = ex2f(ma - mna), ab = ex2f(mb - mnb);
        ma = mna; mb = mnb;
        float rsa = 0.f, rsb = 0.f;
        #pragma unroll
        for (int nf = 0; nf < 8; nf++) {
            sc[nf][0] = ex2f(sc[nf][0] - mna);
            sc[nf][1] = ex2f(sc[nf][1] - mna);
            sc[nf][2] = ex2f(sc[nf][2] - mnb);
            sc[nf][3] = ex2f(sc[nf][3] - mnb);
            rsa += sc[nf][0] + sc[nf][1];
            rsb += sc[nf][2] + sc[nf][3];
        }
        rsa += __shfl_xor_sync(0xffffffffu, rsa, 1);
        rsa += __shfl_xor_sync(0xffffffffu, rsa, 2);
        rsb += __shfl_xor_sync(0xffffffffu, rsb, 1);
        rsb += __shfl_xor_sync(0xffffffffu, rsb, 2);
        la = la * aa + rsa;
        lb = lb * ab + rsb;
        #pragma unroll
        for (int nf = 0; nf < 8; nf++) {
            O[nf][0] *= aa; O[nf][1] *= aa;
            O[nf][2] *= ab; O[nf][3] *= ab;
        }

        // ---- P @ V ----
        #pragma unroll
        for (int ks = 0; ks < 4; ks++) {
            const uint32_t kb = (uint32_t)ks * 32;
            uint32_t ph[4], pl[4];
            ph[0] = pack_bf16x2(sc[2 * ks][0],     sc[2 * ks][1],     pl[0]);
            ph[1] = pack_bf16x2(sc[2 * ks][2],     sc[2 * ks][3],     pl[1]);
            ph[2] = pack_bf16x2(sc[2 * ks + 1][0], sc[2 * ks + 1][1], pl[2]);
            ph[3] = pack_bf16x2(sc[2 * ks + 1][2], sc[2 * ks + 1][3], pl[3]);

            #pragma unroll
            for (int nfp = 0; nfp < 4; nfp++) {
                uint32_t vh4[4], vl4[4];
                ldsm4(vh4, sbu + 2 * PLANE * 2 + fragOff[nfp] + kb);
                ldsm4(vl4, sbu + 3 * PLANE * 2 + fragOff[nfp] + kb);
                #pragma unroll
                for (int j = 0; j < 2; j++) {
                    const int nf = 2 * nfp + j;
                    mma_bf16(O[nf], ph, vh4 + 2 * j);
                    mma_bf16(O[nf], ph, vl4 + 2 * j);
                    mma_bf16(O[nf], pl, vh4 + 2 * j);
                }
            }
        }
        __syncthreads();
    }

    // ---- epilogue: X bf16 hi/lo planes ----
    float ia = 1.0f / la, ib = 1.0f / lb;
    #pragma unroll
    for (int nf = 0; nf < 8; nf++) {
        int c = nf * 8 + 2 * t;
        size_t a0 = hb + (size_t)r0 * 64 + c;
        size_t a1 = hb + (size_t)(r0 + 8) * 64 + c;
        uint32_t lo0, lo1;
        uint32_t hi0 = pack_bf16x2(O[nf][0] * ia, O[nf][1] * ia, lo0);
        uint32_t hi1 = pack_bf16x2(O[nf][2] * ib, O[nf][3] * ib, lo1);
        *reinterpret_cast<uint32_t*>(g_Xh + a0) = hi0;
        *reinterpret_cast<uint32_t*>(g_Xl + a0) = lo0;
        *reinterpret_cast<uint32_t*>(g_Xh + a1) = hi1;
        *reinterpret_cast<uint32_t*>(g_Xl + a1) = lo1;
    }
}

// ---------------------------------------------------------------------------
extern "C" void kernel_launch(void* const* d_in, const int* in_sizes, int n_in,
                              void* d_out, int out_size)
{
    const float* Q  = (const float*)d_in[0];
    const float* K  = (const float*)d_in[1];
    const float* V  = (const float*)d_in[2];
    const float* Wq = (const float*)d_in[3];
    const float* bq = (const float*)d_in[4];
    const float* Wk = (const float*)d_in[5];
    const float* bk = (const float*)d_in[6];
    const float* Wv = (const float*)d_in[7];
    const float* bv = (const float*)d_in[8];
    const float* Wo = (const float*)d_in[9];
    const float* bo = (const float*)d_in[10];
    float* out = (float*)d_out;

    // 0) weight transpose + bf16 split
    prep_weights<<<4096, 256>>>(Wq, Wk, Wv, Wo);

    // 1) QKV projections -> bf16 hi/lo planes
    cudaFuncSetAttribute(proj_mma, cudaFuncAttributeMaxDynamicSharedMemorySize, GEMM_SMEM);
    proj_mma<<<dim3(S / 128, B * H, 3), 256, GEMM_SMEM>>>(Q, K, V, bq, bk, bv);

    // 2) attention (KV tile 64, ldmatrix feeds)
    cudaFuncSetAttribute(attn_mma, cudaFuncAttributeMaxDynamicSharedMemorySize, ATTN_SMEM);
    attn_mma<<<dim3(S / 64, B * H), 128, ATTN_SMEM>>>();

    // 3) output projection from X planes
    cudaFuncSetAttribute(oproj_mma, cudaFuncAttributeMaxDynamicSharedMemorySize, GEMM_SMEM);
    oproj_mma<<<dim3(512 / 64, 1024 / 128, B), 256, GEMM_SMEM>>>(bo, out);
}